// round 1
// baseline (speedup 1.0000x reference)
#include <cuda_runtime.h>
#include <stdint.h>

// Problem shape (fixed by the dataset): x,y are [4096, 3072] fp32, buffers length 50000.
#define D_DIM 3072
#define NB    4096

// Scratch (no cudaMalloc allowed -> __device__ globals)
__device__ float g_x2[NB];
__device__ float g_y2[NB];
__device__ unsigned long long g_best[NB];   // packed (float_bits(v) << 32) | col_index

// ---------------------------------------------------------------------------
// Row squared-norms for x (blocks [0,NB)) and y (blocks [NB,2NB))
// ---------------------------------------------------------------------------
__global__ void norms_kernel(const float* __restrict__ x, const float* __restrict__ y) {
    int row = blockIdx.x;
    const float* p = (row < NB) ? (x + (size_t)row * D_DIM)
                                : (y + (size_t)(row - NB) * D_DIM);
    const float4* p4 = (const float4*)p;
    float s = 0.f;
    #pragma unroll 3
    for (int k = threadIdx.x; k < D_DIM / 4; k += 256) {
        float4 v = p4[k];
        s += v.x * v.x + v.y * v.y + v.z * v.z + v.w * v.w;
    }
    __shared__ float sm[256];
    sm[threadIdx.x] = s;
    __syncthreads();
    for (int o = 128; o > 0; o >>= 1) {
        if (threadIdx.x < o) sm[threadIdx.x] += sm[threadIdx.x + o];
        __syncthreads();
    }
    if (threadIdx.x == 0) {
        if (row < NB) g_x2[row] = sm[0];
        else          g_y2[row - NB] = sm[0];
    }
}

// ---------------------------------------------------------------------------
// Copy passthrough outputs (out is poisoned) + reset the argmin scratch
// out[0:N)      = min_dists (float)
// out[N:2N)     = nn_indices converted to float
// ---------------------------------------------------------------------------
__global__ void init_out_kernel(const float* __restrict__ md, const int* __restrict__ ni,
                                float* __restrict__ out, int N) {
    int i = blockIdx.x * blockDim.x + threadIdx.x;
    if (i < N) {
        out[i]     = md[i];
        out[N + i] = (float)ni[i];
    }
    if (i < NB) g_best[i] = 0xFFFFFFFFFFFFFFFFULL;
}

// ---------------------------------------------------------------------------
// Fused GEMM + per-row (min, argmin) over v = y2[j] - 2*dot(x_i, y_j).
// 128x128 tile per block, 8x8 per thread, K-step 8, fp32 FFMA accumulation.
// ---------------------------------------------------------------------------
__global__ __launch_bounds__(256, 2)
void gemm_min_kernel(const float* __restrict__ X, const float* __restrict__ Y) {
    __shared__ float As[8][128];
    __shared__ float Bs[8][128];

    const int t  = threadIdx.x;
    const int tx = t & 15;        // 16 thread-cols
    const int ty = t >> 4;        // 16 thread-rows
    const int bm = blockIdx.y * 128;
    const int bn = blockIdx.x * 128;

    // Global-load assignment: 128 rows x 8 k, one float4 per thread per tile.
    const int lrow = t >> 1;            // 0..127
    const int kq4  = t & 1;             // which float4 of the 8-wide k chunk
    const float4* Xr = (const float4*)(X + (size_t)(bm + lrow) * D_DIM) + kq4;
    const float4* Yr = (const float4*)(Y + (size_t)(bn + lrow) * D_DIM) + kq4;

    float acc[8][8];
    #pragma unroll
    for (int i = 0; i < 8; i++)
        #pragma unroll
        for (int j = 0; j < 8; j++) acc[i][j] = 0.f;

    float4 xa = Xr[0];
    float4 yb = Yr[0];

    for (int k0 = 0; k0 < D_DIM; k0 += 8) {
        __syncthreads();                       // previous tile fully consumed
        const int ks = kq4 * 4;
        As[ks + 0][lrow] = xa.x; As[ks + 1][lrow] = xa.y;
        As[ks + 2][lrow] = xa.z; As[ks + 3][lrow] = xa.w;
        Bs[ks + 0][lrow] = yb.x; Bs[ks + 1][lrow] = yb.y;
        Bs[ks + 2][lrow] = yb.z; Bs[ks + 3][lrow] = yb.w;
        __syncthreads();

        if (k0 + 8 < D_DIM) {                  // prefetch next tile into regs
            xa = Xr[(k0 + 8) >> 2];
            yb = Yr[(k0 + 8) >> 2];
        }

        #pragma unroll
        for (int kk = 0; kk < 8; kk++) {
            float4 a0 = *(const float4*)&As[kk][ty * 8];
            float4 a1 = *(const float4*)&As[kk][ty * 8 + 4];
            float4 b0 = *(const float4*)&Bs[kk][tx * 8];
            float4 b1 = *(const float4*)&Bs[kk][tx * 8 + 4];
            float a[8] = {a0.x, a0.y, a0.z, a0.w, a1.x, a1.y, a1.z, a1.w};
            float b[8] = {b0.x, b0.y, b0.z, b0.w, b1.x, b1.y, b1.z, b1.w};
            #pragma unroll
            for (int i = 0; i < 8; i++)
                #pragma unroll
                for (int j = 0; j < 8; j++)
                    acc[i][j] = fmaf(a[i], b[j], acc[i][j]);
        }
    }

    // Epilogue: per-row min over this block's 128 columns, then global atomicMin.
    float y2r[8];
    #pragma unroll
    for (int j = 0; j < 8; j++) y2r[j] = g_y2[bn + tx * 8 + j];

    #pragma unroll
    for (int i = 0; i < 8; i++) {
        float vmin = 3.4e38f;
        int   jmin = 0;
        #pragma unroll
        for (int j = 0; j < 8; j++) {
            float v = y2r[j] - 2.f * acc[i][j];   // x2 is row-constant: same argmin
            if (v < vmin) { vmin = v; jmin = bn + tx * 8 + j; }
        }
        // v > 0 always here (y2 ~ 3072 >> 2|dot|), so float-bit order == value order.
        unsigned long long key =
            ((unsigned long long)__float_as_uint(vmin) << 32) | (unsigned)jmin;
        // Reduce across the 16 threads covering this row (same ty, contiguous lanes).
        #pragma unroll
        for (int o = 8; o > 0; o >>= 1) {
            unsigned long long other = __shfl_xor_sync(0xffffffffu, key, o);
            if (other < key) key = other;     // ties -> smaller j (first occurrence)
        }
        if (tx == 0) atomicMin(&g_best[bm + ty * 8 + i], key);
    }
}

// ---------------------------------------------------------------------------
// Finalize: dist = sqrt(max(x2 + v, 0)); min-update dists, overwrite indices.
// Scalars x_idx_start / y_idx_start read on-device (graph-capture safe).
// ---------------------------------------------------------------------------
__global__ void final_kernel(const float* __restrict__ md, float* __restrict__ out,
                             int N, const int* __restrict__ xs, const int* __restrict__ ys) {
    int i = blockIdx.x * blockDim.x + threadIdx.x;
    if (i >= NB) return;
    const int x0 = xs[0];
    const int y0 = ys[0];
    unsigned long long key = g_best[i];
    float v = __uint_as_float((unsigned)(key >> 32));
    int   j = (int)(unsigned)(key & 0xffffffffULL);
    float d2   = g_x2[i] + v;
    float dist = sqrtf(fmaxf(d2, 0.f));
    float old  = md[x0 + i];
    out[x0 + i]     = fminf(dist, old);         // min with existing slice
    out[N + x0 + i] = (float)(j + y0);          // unconditional index overwrite
}

// ---------------------------------------------------------------------------
extern "C" void kernel_launch(void* const* d_in, const int* in_sizes, int n_in,
                              void* d_out, int out_size) {
    const float* x  = (const float*)d_in[0];
    const float* y  = (const float*)d_in[1];
    const float* md = (const float*)d_in[2];
    const int*   ni = (const int*)d_in[3];
    const int*   xs = (const int*)d_in[4];
    const int*   ys = (const int*)d_in[5];
    float* out = (float*)d_out;
    const int N = in_sizes[2];   // 50000

    norms_kernel<<<2 * NB, 256>>>(x, y);
    init_out_kernel<<<(N + 255) / 256, 256>>>(md, ni, out, N);
    dim3 grid(NB / 128, NB / 128);
    gemm_min_kernel<<<grid, 256>>>(x, y);
    final_kernel<<<(NB + 255) / 256, 256>>>(md, out, N, xs, ys);
}